// round 7
// baseline (speedup 1.0000x reference)
#include <cuda_runtime.h>
#include <cstdint>

#define NCLS   10
#define BLOCK  256
#define NGRID  (152 * 4)     // 4 blocks/SM @ <=64 regs -> exactly one wave
#define NWARPS (BLOCK / 32)

typedef unsigned long long ull;

__device__ float2       g_part[NGRID][NCLS];
__device__ unsigned int g_ticket = 0;

#define PACKED_ONES 0x3F8000003F800000ull   // {1.0f, 1.0f}

// One element -> 10 register accumulators; single fused asm block.
// Per class: setp.eq + predicated fma.rn.f32x2 (single SASS FFMA2):
//   acc[c] += inc * {1,1}   where inc = {sq, 1.0f}.
__device__ __forceinline__ void acc_el(float o, float t, int m, ull* a, ull ones) {
    float e  = o - t;
    float sq = e * e;
    int  key = (m == 1) ? (int)t : NCLS;   // dummy key 10 matches no class
    asm volatile(
        "{\n\t"
        ".reg .pred p;\n\t"
        ".reg .b64  inc;\n\t"
        "mov.b64 inc, {%10, %11};\n\t"
        "setp.eq.s32 p, %12, 0;\n\t @p fma.rn.f32x2 %0, inc, %13, %0;\n\t"
        "setp.eq.s32 p, %12, 1;\n\t @p fma.rn.f32x2 %1, inc, %13, %1;\n\t"
        "setp.eq.s32 p, %12, 2;\n\t @p fma.rn.f32x2 %2, inc, %13, %2;\n\t"
        "setp.eq.s32 p, %12, 3;\n\t @p fma.rn.f32x2 %3, inc, %13, %3;\n\t"
        "setp.eq.s32 p, %12, 4;\n\t @p fma.rn.f32x2 %4, inc, %13, %4;\n\t"
        "setp.eq.s32 p, %12, 5;\n\t @p fma.rn.f32x2 %5, inc, %13, %5;\n\t"
        "setp.eq.s32 p, %12, 6;\n\t @p fma.rn.f32x2 %6, inc, %13, %6;\n\t"
        "setp.eq.s32 p, %12, 7;\n\t @p fma.rn.f32x2 %7, inc, %13, %7;\n\t"
        "setp.eq.s32 p, %12, 8;\n\t @p fma.rn.f32x2 %8, inc, %13, %8;\n\t"
        "setp.eq.s32 p, %12, 9;\n\t @p fma.rn.f32x2 %9, inc, %13, %9;\n\t"
        "}"
        : "+l"(a[0]), "+l"(a[1]), "+l"(a[2]), "+l"(a[3]), "+l"(a[4]),
          "+l"(a[5]), "+l"(a[6]), "+l"(a[7]), "+l"(a[8]), "+l"(a[9])
        : "f"(sq), "f"(1.0f), "r"(key), "l"(ones));
}

__global__ __launch_bounds__(BLOCK, 4) void loss_k(
    const float* __restrict__ outs,
    const float* __restrict__ tgts,
    const int*   __restrict__ mask,
    int n, float* __restrict__ out, int out_size)
{
    __shared__ float2 s_warp[NWARPS][NCLS];
    __shared__ float  le[NCLS];
    __shared__ unsigned int s_ticket;
    const int tid  = threadIdx.x;
    const int lane = tid & 31;
    const int wid  = tid >> 5;
    const ull ones = PACKED_ONES;

    ull acc[NCLS];
    #pragma unroll
    for (int c = 0; c < NCLS; c++) acc[c] = 0ull;   // {0.0f, 0.0f}

    const int n4 = n >> 2;
    const float4* __restrict__ o4 = reinterpret_cast<const float4*>(outs);
    const float4* __restrict__ t4 = reinterpret_cast<const float4*>(tgts);
    const int4*   __restrict__ m4 = reinterpret_cast<const int4*>(mask);

    const int stride = NGRID * BLOCK;
    int i = blockIdx.x * BLOCK + tid;

    // Register double-buffer: prefetch iteration i+1 before processing i.
    float4 ov, tv; int4 mv;
    if (i < n4) { ov = o4[i]; tv = t4[i]; mv = m4[i]; }
    for (; i < n4; ) {
        int inext = i + stride;
        float4 ovn, tvn; int4 mvn;
        if (inext < n4) { ovn = o4[inext]; tvn = t4[inext]; mvn = m4[inext]; }
        acc_el(ov.x, tv.x, mv.x, acc, ones);
        acc_el(ov.y, tv.y, mv.y, acc, ones);
        acc_el(ov.z, tv.z, mv.z, acc, ones);
        acc_el(ov.w, tv.w, mv.w, acc, ones);
        ov = ovn; tv = tvn; mv = mvn;
        i = inext;
    }
    if (blockIdx.x == 0) {               // scalar tail (n % 4)
        int j = (n4 << 2) + tid;
        if (j < n) acc_el(outs[j], tgts[j], mask[j], acc, ones);
    }

    // ---- warp shuffle reduction (float2 packed in ull) ----
    #pragma unroll
    for (int off = 16; off > 0; off >>= 1) {
        #pragma unroll
        for (int c = 0; c < NCLS; c++) {
            ull other = __shfl_down_sync(0xffffffffu, acc[c], off);
            asm("fma.rn.f32x2 %0, %1, %2, %0;" : "+l"(acc[c]) : "l"(other), "l"(ones));
        }
    }
    if (lane == 0) {
        #pragma unroll
        for (int c = 0; c < NCLS; c++) {
            float2 v;
            asm("mov.b64 {%0, %1}, %2;" : "=f"(v.x), "=f"(v.y) : "l"(acc[c]));
            s_warp[wid][c] = v;
        }
    }
    __syncthreads();

    // ---- per-block partial: threads 0..9 combine the warp rows ----
    if (tid < NCLS) {
        float2 p = make_float2(0.0f, 0.0f);
        #pragma unroll
        for (int w = 0; w < NWARPS; w++) {
            float2 v = s_warp[w][tid];
            p.x += v.x; p.y += v.y;
        }
        g_part[blockIdx.x][tid] = p;
    }
    __threadfence();
    __syncthreads();
    if (tid == 0) s_ticket = atomicAdd(&g_ticket, 1u);
    __syncthreads();
    if (s_ticket != (unsigned)(gridDim.x - 1)) return;

    // ---- last block: reduce partials, finalize, write output ----
    __threadfence();

    float2 racc[NCLS];
    #pragma unroll
    for (int c = 0; c < NCLS; c++) racc[c] = make_float2(0.0f, 0.0f);
    for (int j = tid; j < NGRID; j += BLOCK) {
        #pragma unroll
        for (int c = 0; c < NCLS; c++) {
            float2 p = g_part[j][c];
            racc[c].x += p.x;
            racc[c].y += p.y;
        }
    }
    #pragma unroll
    for (int off = 16; off > 0; off >>= 1) {
        #pragma unroll
        for (int c = 0; c < NCLS; c++) {
            racc[c].x += __shfl_down_sync(0xffffffffu, racc[c].x, off);
            racc[c].y += __shfl_down_sync(0xffffffffu, racc[c].y, off);
        }
    }
    if (lane == 0) {
        #pragma unroll
        for (int c = 0; c < NCLS; c++) s_warp[wid][c] = racc[c];
    }
    __syncthreads();

    if (tid < NCLS) {
        float2 tot = make_float2(0.0f, 0.0f);
        #pragma unroll
        for (int w = 0; w < NWARPS; w++) {
            float2 v = s_warp[w][tid];
            tot.x += v.x; tot.y += v.y;
        }
        s_warp[0][tid] = tot;
        le[tid] = (tot.y > 0.0f) ? (tot.x / fmaxf(tot.y, 1.0f)) : 0.0f;
    }
    __syncthreads();

    if (tid == 0) {
        float loss = 0.0f;
        #pragma unroll
        for (int c = 0; c < NCLS; c++) loss += 0.1f * le[c];
        out[0] = loss;
        g_ticket = 0;    // reset for graph replay determinism
    } else if (tid >= 1 && tid <= NCLS) {
        out[tid] = le[tid - 1];                  // loss_each
    } else if (tid >= NCLS + 1 && tid <= 2 * NCLS) {
        out[tid] = s_warp[0][tid - NCLS - 1].y;  // class_n
    } else if (tid < out_size) {
        out[tid] = 0.0f;
    }
}

extern "C" void kernel_launch(void* const* d_in, const int* in_sizes, int n_in,
                              void* d_out, int out_size) {
    const float* outs = (const float*)d_in[0];
    const float* tgts = (const float*)d_in[1];
    const int*   mask = (const int*)d_in[2];
    float* out = (float*)d_out;
    int n = in_sizes[0];

    loss_k<<<NGRID, BLOCK>>>(outs, tgts, mask, n, out, out_size);
}

// round 8
// speedup vs baseline: 1.1341x; 1.1341x over previous
#include <cuda_runtime.h>
#include <cstdint>

#define NCLS   10
#define BLOCK  256
#define NGRID  (152 * 4)     // 4 blocks/SM @ <=64 regs -> exactly one wave
#define NWARPS (BLOCK / 32)

typedef unsigned long long ull;

__device__ float2       g_part[NGRID][NCLS];
__device__ unsigned int g_ticket = 0;

#define PACKED_ONES 0x3F8000003F800000ull   // {1.0f, 1.0f}

// One element -> 10 register accumulators; single fused asm block.
// Guards are FSETP.EQ.AND on the float target directly (fma pipe, valid folded):
//   pv = (m == 1);  for c: p = (t == c) && pv;  @p acc[c] += {sq,1} * {1,1}
// No F2I, no int key, no dummy class; ALU usage ~1 op/element.
__device__ __forceinline__ void acc_el(float o, float t, int m, ull* a, ull ones) {
    float e  = o - t;
    float sq = e * e;
    asm volatile(
        "{\n\t"
        ".reg .pred pv, p;\n\t"
        ".reg .b64  inc;\n\t"
        "setp.eq.s32 pv, %12, 1;\n\t"
        "mov.b64 inc, {%10, %11};\n\t"
        "setp.eq.and.f32 p, %13, 0F00000000, pv;\n\t @p fma.rn.f32x2 %0, inc, %14, %0;\n\t"
        "setp.eq.and.f32 p, %13, 0F3F800000, pv;\n\t @p fma.rn.f32x2 %1, inc, %14, %1;\n\t"
        "setp.eq.and.f32 p, %13, 0F40000000, pv;\n\t @p fma.rn.f32x2 %2, inc, %14, %2;\n\t"
        "setp.eq.and.f32 p, %13, 0F40400000, pv;\n\t @p fma.rn.f32x2 %3, inc, %14, %3;\n\t"
        "setp.eq.and.f32 p, %13, 0F40800000, pv;\n\t @p fma.rn.f32x2 %4, inc, %14, %4;\n\t"
        "setp.eq.and.f32 p, %13, 0F40A00000, pv;\n\t @p fma.rn.f32x2 %5, inc, %14, %5;\n\t"
        "setp.eq.and.f32 p, %13, 0F40C00000, pv;\n\t @p fma.rn.f32x2 %6, inc, %14, %6;\n\t"
        "setp.eq.and.f32 p, %13, 0F40E00000, pv;\n\t @p fma.rn.f32x2 %7, inc, %14, %7;\n\t"
        "setp.eq.and.f32 p, %13, 0F41000000, pv;\n\t @p fma.rn.f32x2 %8, inc, %14, %8;\n\t"
        "setp.eq.and.f32 p, %13, 0F41100000, pv;\n\t @p fma.rn.f32x2 %9, inc, %14, %9;\n\t"
        "}"
        : "+l"(a[0]), "+l"(a[1]), "+l"(a[2]), "+l"(a[3]), "+l"(a[4]),
          "+l"(a[5]), "+l"(a[6]), "+l"(a[7]), "+l"(a[8]), "+l"(a[9])
        : "f"(sq), "f"(1.0f), "r"(m), "f"(t), "l"(ones));
}

__global__ __launch_bounds__(BLOCK, 4) void loss_k(
    const float* __restrict__ outs,
    const float* __restrict__ tgts,
    const int*   __restrict__ mask,
    int n, float* __restrict__ out, int out_size)
{
    __shared__ float2 s_warp[NWARPS][NCLS];
    __shared__ float  le[NCLS];
    __shared__ unsigned int s_ticket;
    const int tid  = threadIdx.x;
    const int lane = tid & 31;
    const int wid  = tid >> 5;
    const ull ones = PACKED_ONES;

    ull acc[NCLS];
    #pragma unroll
    for (int c = 0; c < NCLS; c++) acc[c] = 0ull;   // {0.0f, 0.0f}

    const int n4 = n >> 2;
    const float4* __restrict__ o4 = reinterpret_cast<const float4*>(outs);
    const float4* __restrict__ t4 = reinterpret_cast<const float4*>(tgts);
    const int4*   __restrict__ m4 = reinterpret_cast<const int4*>(mask);

    const int stride = NGRID * BLOCK;
    int i = blockIdx.x * BLOCK + tid;

    // unroll x2: 6 front-batched LDG.128 per iteration (best config from R4)
    for (; i + stride < n4; i += 2 * stride) {
        float4 ov0 = o4[i];
        float4 ov1 = o4[i + stride];
        float4 tv0 = t4[i];
        float4 tv1 = t4[i + stride];
        int4   mv0 = m4[i];
        int4   mv1 = m4[i + stride];
        acc_el(ov0.x, tv0.x, mv0.x, acc, ones);
        acc_el(ov0.y, tv0.y, mv0.y, acc, ones);
        acc_el(ov0.z, tv0.z, mv0.z, acc, ones);
        acc_el(ov0.w, tv0.w, mv0.w, acc, ones);
        acc_el(ov1.x, tv1.x, mv1.x, acc, ones);
        acc_el(ov1.y, tv1.y, mv1.y, acc, ones);
        acc_el(ov1.z, tv1.z, mv1.z, acc, ones);
        acc_el(ov1.w, tv1.w, mv1.w, acc, ones);
    }
    if (i < n4) {
        float4 ov = o4[i];
        float4 tv = t4[i];
        int4   mv = m4[i];
        acc_el(ov.x, tv.x, mv.x, acc, ones);
        acc_el(ov.y, tv.y, mv.y, acc, ones);
        acc_el(ov.z, tv.z, mv.z, acc, ones);
        acc_el(ov.w, tv.w, mv.w, acc, ones);
    }
    if (blockIdx.x == 0) {               // scalar tail (n % 4)
        int j = (n4 << 2) + tid;
        if (j < n) acc_el(outs[j], tgts[j], mask[j], acc, ones);
    }

    // ---- warp shuffle reduction (float2 packed in ull) ----
    #pragma unroll
    for (int off = 16; off > 0; off >>= 1) {
        #pragma unroll
        for (int c = 0; c < NCLS; c++) {
            ull other = __shfl_down_sync(0xffffffffu, acc[c], off);
            asm("fma.rn.f32x2 %0, %1, %2, %0;" : "+l"(acc[c]) : "l"(other), "l"(ones));
        }
    }
    if (lane == 0) {
        #pragma unroll
        for (int c = 0; c < NCLS; c++) {
            float2 v;
            asm("mov.b64 {%0, %1}, %2;" : "=f"(v.x), "=f"(v.y) : "l"(acc[c]));
            s_warp[wid][c] = v;
        }
    }
    __syncthreads();

    // ---- per-block partial: threads 0..9 combine the warp rows ----
    if (tid < NCLS) {
        float2 p = make_float2(0.0f, 0.0f);
        #pragma unroll
        for (int w = 0; w < NWARPS; w++) {
            float2 v = s_warp[w][tid];
            p.x += v.x; p.y += v.y;
        }
        g_part[blockIdx.x][tid] = p;
    }
    __threadfence();
    __syncthreads();
    if (tid == 0) s_ticket = atomicAdd(&g_ticket, 1u);
    __syncthreads();
    if (s_ticket != (unsigned)(gridDim.x - 1)) return;

    // ---- last block: reduce partials, finalize, write output ----
    __threadfence();

    float2 racc[NCLS];
    #pragma unroll
    for (int c = 0; c < NCLS; c++) racc[c] = make_float2(0.0f, 0.0f);
    for (int j = tid; j < NGRID; j += BLOCK) {
        #pragma unroll
        for (int c = 0; c < NCLS; c++) {
            float2 p = g_part[j][c];
            racc[c].x += p.x;
            racc[c].y += p.y;
        }
    }
    #pragma unroll
    for (int off = 16; off > 0; off >>= 1) {
        #pragma unroll
        for (int c = 0; c < NCLS; c++) {
            racc[c].x += __shfl_down_sync(0xffffffffu, racc[c].x, off);
            racc[c].y += __shfl_down_sync(0xffffffffu, racc[c].y, off);
        }
    }
    if (lane == 0) {
        #pragma unroll
        for (int c = 0; c < NCLS; c++) s_warp[wid][c] = racc[c];
    }
    __syncthreads();

    if (tid < NCLS) {
        float2 tot = make_float2(0.0f, 0.0f);
        #pragma unroll
        for (int w = 0; w < NWARPS; w++) {
            float2 v = s_warp[w][tid];
            tot.x += v.x; tot.y += v.y;
        }
        s_warp[0][tid] = tot;
        le[tid] = (tot.y > 0.0f) ? (tot.x / fmaxf(tot.y, 1.0f)) : 0.0f;
    }
    __syncthreads();

    if (tid == 0) {
        float loss = 0.0f;
        #pragma unroll
        for (int c = 0; c < NCLS; c++) loss += 0.1f * le[c];
        out[0] = loss;
        g_ticket = 0;    // reset for graph replay determinism
    } else if (tid >= 1 && tid <= NCLS) {
        out[tid] = le[tid - 1];                  // loss_each
    } else if (tid >= NCLS + 1 && tid <= 2 * NCLS) {
        out[tid] = s_warp[0][tid - NCLS - 1].y;  // class_n
    } else if (tid < out_size) {
        out[tid] = 0.0f;
    }
}

extern "C" void kernel_launch(void* const* d_in, const int* in_sizes, int n_in,
                              void* d_out, int out_size) {
    const float* outs = (const float*)d_in[0];
    const float* tgts = (const float*)d_in[1];
    const int*   mask = (const int*)d_in[2];
    float* out = (float*)d_out;
    int n = in_sizes[0];

    loss_k<<<NGRID, BLOCK>>>(outs, tgts, mask, n, out, out_size);
}